// round 1
// baseline (speedup 1.0000x reference)
#include <cuda_runtime.h>
#include <cstdint>

#define SEQ     4096
#define DMODEL  1024
#define NHEADS  16
#define DH      64
#define QKVDIM  (3 * DMODEL)

// ---------------- scratch ----------------
__device__ float g_qkv[(size_t)SEQ * QKVDIM];   // [n][3*1024]
__device__ float g_ctx[(size_t)SEQ * DMODEL];   // [n][h*64+d]

// ============================================================
// SGEMM: C[M,N] = A[M,K] * B[N,K]^T + bias[N]
// 128x128 tile, K-step 8, 256 threads, 8x8 per thread (split 4+4)
// ============================================================
__global__ __launch_bounds__(256)
void sgemm_nt_bias(const float* __restrict__ A, const float* __restrict__ B,
                   const float* __restrict__ bias, float* __restrict__ C,
                   int M, int N, int K)
{
    __shared__ float As[8][128];
    __shared__ float Bs[8][128];

    const int tid = threadIdx.x;
    const int bm = blockIdx.y * 128;
    const int bn = blockIdx.x * 128;

    const int lr = tid >> 1;          // 0..127
    const int lc = (tid & 1) * 4;     // 0 or 4

    const float* Ag = A + (size_t)(bm + lr) * K + lc;
    const float* Bg = B + (size_t)(bn + lr) * K + lc;

    const int tx = tid & 15;
    const int ty = tid >> 4;

    float acc[8][8];
#pragma unroll
    for (int i = 0; i < 8; i++)
#pragma unroll
        for (int j = 0; j < 8; j++) acc[i][j] = 0.0f;

    for (int kt = 0; kt < K; kt += 8) {
        float4 av = *(const float4*)(Ag + kt);
        float4 bv = *(const float4*)(Bg + kt);
        __syncthreads();
        As[lc + 0][lr] = av.x; As[lc + 1][lr] = av.y;
        As[lc + 2][lr] = av.z; As[lc + 3][lr] = av.w;
        Bs[lc + 0][lr] = bv.x; Bs[lc + 1][lr] = bv.y;
        Bs[lc + 2][lr] = bv.z; Bs[lc + 3][lr] = bv.w;
        __syncthreads();

#pragma unroll
        for (int kk = 0; kk < 8; kk++) {
            float a[8], b[8];
            *(float4*)(a)     = *(const float4*)&As[kk][ty * 4];
            *(float4*)(a + 4) = *(const float4*)&As[kk][64 + ty * 4];
            *(float4*)(b)     = *(const float4*)&Bs[kk][tx * 4];
            *(float4*)(b + 4) = *(const float4*)&Bs[kk][64 + tx * 4];
#pragma unroll
            for (int i = 0; i < 8; i++)
#pragma unroll
                for (int j = 0; j < 8; j++)
                    acc[i][j] = fmaf(a[i], b[j], acc[i][j]);
        }
    }

    float bias0[4], bias1[4];
    *(float4*)bias0 = *(const float4*)&bias[bn + tx * 4];
    *(float4*)bias1 = *(const float4*)&bias[bn + 64 + tx * 4];

#pragma unroll
    for (int i = 0; i < 8; i++) {
        int row = bm + ((i < 4) ? (ty * 4 + i) : (64 + ty * 4 + i - 4));
        float4 o0, o1;
        o0.x = acc[i][0] + bias0[0]; o0.y = acc[i][1] + bias0[1];
        o0.z = acc[i][2] + bias0[2]; o0.w = acc[i][3] + bias0[3];
        o1.x = acc[i][4] + bias1[0]; o1.y = acc[i][5] + bias1[1];
        o1.z = acc[i][6] + bias1[2]; o1.w = acc[i][7] + bias1[3];
        *(float4*)&C[(size_t)row * N + bn + tx * 4]      = o0;
        *(float4*)&C[(size_t)row * N + bn + 64 + tx * 4] = o1;
    }
}

// ============================================================
// Flash attention, fp32. One CTA per (64-query block, head).
// Online softmax over 64-key tiles. Q/K/P stored transposed in
// padded smem so inner products use LDS.128.
// ============================================================
#define BM 64
#define BN 64
#define SP 68   // padded stride (multiple of 4 for float4 alignment)

__global__ __launch_bounds__(256)
void flash_attn_kernel(const float* __restrict__ qkv, float* __restrict__ ctx)
{
    extern __shared__ float sm[];
    float* Qt = sm;                      // [DH][SP]  Qt[d*SP+r] = Q[r][d]/8
    float* Kt = sm + DH * SP;            // [DH][SP]
    float* Vs = sm + 2 * DH * SP;        // [BN][SP]  Vs[r*SP+d]
    float* Pt = sm + 3 * DH * SP;        // [BN][SP]  Pt[j*SP+i] = P[i][j]

    const int h  = blockIdx.y;
    const int qb = blockIdx.x;
    const int tid = threadIdx.x;
    const int tx = tid & 15;
    const int ty = tid >> 4;

    const size_t rs = QKVDIM;
    const float* qbase = qkv + (size_t)qb * BM * rs + h * DH;
    const float* kbase = qkv + DMODEL + (size_t)h * DH;
    const float* vbase = qkv + 2 * DMODEL + (size_t)h * DH;

    // load Q transposed, pre-scaled by 1/8
    for (int i = tid; i < BM * (DH / 4); i += 256) {
        int r = i >> 4;
        int c = (i & 15) << 2;
        float4 v = *(const float4*)(qbase + (size_t)r * rs + c);
        Qt[(c + 0) * SP + r] = v.x * 0.125f;
        Qt[(c + 1) * SP + r] = v.y * 0.125f;
        Qt[(c + 2) * SP + r] = v.z * 0.125f;
        Qt[(c + 3) * SP + r] = v.w * 0.125f;
    }

    float m[4], l[4], o[4][4];
#pragma unroll
    for (int i = 0; i < 4; i++) {
        m[i] = -1e30f; l[i] = 0.0f;
#pragma unroll
        for (int j = 0; j < 4; j++) o[i][j] = 0.0f;
    }

    for (int kt = 0; kt < SEQ; kt += BN) {
        __syncthreads();   // protect Kt/Vs/Pt (also covers initial Q stores)

        // load K (transposed) and V tiles
        for (int i = tid; i < BN * (DH / 4); i += 256) {
            int r = i >> 4;
            int c = (i & 15) << 2;
            const float* kp = kbase + (size_t)(kt + r) * rs + c;
            float4 k4 = *(const float4*)kp;
            Kt[(c + 0) * SP + r] = k4.x;
            Kt[(c + 1) * SP + r] = k4.y;
            Kt[(c + 2) * SP + r] = k4.z;
            Kt[(c + 3) * SP + r] = k4.w;
            float4 v4 = *(const float4*)(vbase + (size_t)(kt + r) * rs + c);
            *(float4*)&Vs[r * SP + c] = v4;
        }
        __syncthreads();

        // S = Q K^T  (4x4 per thread)
        float s[4][4];
#pragma unroll
        for (int i = 0; i < 4; i++)
#pragma unroll
            for (int j = 0; j < 4; j++) s[i][j] = 0.0f;

#pragma unroll 8
        for (int d = 0; d < DH; d++) {
            float4 q4 = *(const float4*)&Qt[d * SP + ty * 4];
            float4 k4 = *(const float4*)&Kt[d * SP + tx * 4];
            float qa[4] = {q4.x, q4.y, q4.z, q4.w};
            float ka[4] = {k4.x, k4.y, k4.z, k4.w};
#pragma unroll
            for (int i = 0; i < 4; i++)
#pragma unroll
                for (int j = 0; j < 4; j++)
                    s[i][j] = fmaf(qa[i], ka[j], s[i][j]);
        }

        // online softmax per row (16 threads share a row, shfl width 16)
#pragma unroll
        for (int i = 0; i < 4; i++) {
            float mx = fmaxf(fmaxf(s[i][0], s[i][1]), fmaxf(s[i][2], s[i][3]));
#pragma unroll
            for (int off = 8; off > 0; off >>= 1)
                mx = fmaxf(mx, __shfl_xor_sync(0xffffffffu, mx, off, 16));
            float mn = fmaxf(m[i], mx);
            float corr = __expf(m[i] - mn);
            float rsum = 0.0f;
#pragma unroll
            for (int j = 0; j < 4; j++) {
                s[i][j] = __expf(s[i][j] - mn);
                rsum += s[i][j];
            }
#pragma unroll
            for (int off = 8; off > 0; off >>= 1)
                rsum += __shfl_xor_sync(0xffffffffu, rsum, off, 16);
            l[i] = l[i] * corr + rsum;
            m[i] = mn;
#pragma unroll
            for (int j = 0; j < 4; j++) o[i][j] *= corr;
        }

        // store P transposed
#pragma unroll
        for (int i = 0; i < 4; i++)
#pragma unroll
            for (int j = 0; j < 4; j++)
                Pt[(tx * 4 + j) * SP + ty * 4 + i] = s[i][j];
        __syncthreads();

        // O += P V
#pragma unroll 8
        for (int jj = 0; jj < BN; jj++) {
            float4 p4 = *(const float4*)&Pt[jj * SP + ty * 4];
            float4 v4 = *(const float4*)&Vs[jj * SP + tx * 4];
            float pa[4] = {p4.x, p4.y, p4.z, p4.w};
            float va[4] = {v4.x, v4.y, v4.z, v4.w};
#pragma unroll
            for (int i = 0; i < 4; i++)
#pragma unroll
                for (int j = 0; j < 4; j++)
                    o[i][j] = fmaf(pa[i], va[j], o[i][j]);
        }
    }

    // epilogue: normalize and write ctx[n][h*64+d]
#pragma unroll
    for (int i = 0; i < 4; i++) {
        float inv = 1.0f / l[i];
        int n = qb * BM + ty * 4 + i;
        float4 out;
        out.x = o[i][0] * inv; out.y = o[i][1] * inv;
        out.z = o[i][2] * inv; out.w = o[i][3] * inv;
        *(float4*)&ctx[(size_t)n * DMODEL + h * DH + tx * 4] = out;
    }
}

// ============================================================
extern "C" void kernel_launch(void* const* d_in, const int* in_sizes, int n_in,
                              void* d_out, int out_size)
{
    const float* x     = (const float*)d_in[0];   // [1,4096,1024]
    const float* w_qkv = (const float*)d_in[1];   // [3072,1024]
    const float* b_qkv = (const float*)d_in[2];   // [3072]
    const float* w_out = (const float*)d_in[3];   // [1024,1024]
    const float* b_out = (const float*)d_in[4];   // [1024]
    float* out = (float*)d_out;                   // [1,4096,1024]

    float* qkv;  cudaGetSymbolAddress((void**)&qkv, g_qkv);
    float* ctx;  cudaGetSymbolAddress((void**)&ctx, g_ctx);

    // 1) QKV projection: [4096,3072]
    {
        dim3 grid(QKVDIM / 128, SEQ / 128);
        sgemm_nt_bias<<<grid, 256>>>(x, w_qkv, b_qkv, qkv, SEQ, QKVDIM, DMODEL);
    }

    // 2) flash attention
    {
        int smem = 4 * DH * SP * (int)sizeof(float);   // 69632 B
        cudaFuncSetAttribute(flash_attn_kernel,
                             cudaFuncAttributeMaxDynamicSharedMemorySize, smem);
        dim3 grid(SEQ / BM, NHEADS);
        flash_attn_kernel<<<grid, 256, smem>>>(qkv, ctx);
    }

    // 3) output projection: [4096,1024]
    {
        dim3 grid(DMODEL / 128, SEQ / 128);
        sgemm_nt_bias<<<grid, 256>>>(ctx, w_out, b_out, out, SEQ, DMODEL, DMODEL);
    }
}

// round 2
// speedup vs baseline: 3.1206x; 3.1206x over previous
#include <cuda_runtime.h>
#include <cuda_bf16.h>
#include <cstdint>

#define SEQ     4096
#define DMODEL  1024
#define NHEADS  16
#define DH      64
#define QKVDIM  (3 * DMODEL)

// ---------------- scratch ----------------
__device__ float g_qkv[(size_t)SEQ * QKVDIM];   // [n][3*1024]
__device__ float g_ctx[(size_t)SEQ * DMODEL];   // [n][h*64+d]

// ============================================================
// helpers
// ============================================================
__device__ __forceinline__ uint32_t smaddr(const void* p) {
    return static_cast<uint32_t>(__cvta_generic_to_shared(p));
}

__device__ __forceinline__ uint32_t b2u(__nv_bfloat162 v) {
    return *reinterpret_cast<uint32_t*>(&v);
}

// split two floats into hi/lo bf16x2 pairs
__device__ __forceinline__ void split2(float x, float y, uint32_t& hi, uint32_t& lo) {
    __nv_bfloat162 h = __float22bfloat162_rn(make_float2(x, y));
    float2 hf = __bfloat1622float2(h);
    __nv_bfloat162 l = __float22bfloat162_rn(make_float2(x - hf.x, y - hf.y));
    hi = b2u(h); lo = b2u(l);
}

// split float4 -> 2 hi uints + 2 lo uints
__device__ __forceinline__ void split4(float4 v, uint32_t* h, uint32_t* l) {
    split2(v.x, v.y, h[0], l[0]);
    split2(v.z, v.w, h[1], l[1]);
}

__device__ __forceinline__ void ldsm_x4(uint32_t* r, uint32_t addr) {
    asm volatile("ldmatrix.sync.aligned.m8n8.x4.shared.b16 {%0,%1,%2,%3}, [%4];"
                 : "=r"(r[0]), "=r"(r[1]), "=r"(r[2]), "=r"(r[3]) : "r"(addr));
}

__device__ __forceinline__ void ldsm_x4_t(uint32_t* r, uint32_t addr) {
    asm volatile("ldmatrix.sync.aligned.m8n8.x4.trans.shared.b16 {%0,%1,%2,%3}, [%4];"
                 : "=r"(r[0]), "=r"(r[1]), "=r"(r[2]), "=r"(r[3]) : "r"(addr));
}

__device__ __forceinline__ void mma_bf16(float* d, const uint32_t* a, uint32_t b0, uint32_t b1) {
    asm volatile(
        "mma.sync.aligned.m16n8k16.row.col.f32.bf16.bf16.f32 "
        "{%0,%1,%2,%3}, {%4,%5,%6,%7}, {%8,%9}, {%0,%1,%2,%3};"
        : "+f"(d[0]), "+f"(d[1]), "+f"(d[2]), "+f"(d[3])
        : "r"(a[0]), "r"(a[1]), "r"(a[2]), "r"(a[3]), "r"(b0), "r"(b1));
}

// ============================================================
// GEMM: C[M,N] = A[M,K]*B[N,K]^T + bias, bf16-split tensor cores
// CTA 128x128, 256 thr (8 warps 2x4), warp 64x32, k-step 16
// ============================================================
#define GST 24   // smem row stride (elems) for 16-elem k tile + pad

__global__ __launch_bounds__(256)
void gemm_bf16s(const float* __restrict__ A, const float* __restrict__ B,
                const float* __restrict__ bias, float* __restrict__ C,
                int M, int N, int K)
{
    __shared__ __nv_bfloat16 Ah[128 * GST], Al[128 * GST];
    __shared__ __nv_bfloat16 Bh[128 * GST], Bl[128 * GST];

    const int tid = threadIdx.x;
    const int w = tid >> 5, lane = tid & 31;
    const int wr = w >> 2, wc = w & 3;
    const int g = lane >> 2, tg = lane & 3;
    const int bm = blockIdx.y * 128, bn = blockIdx.x * 128;

    float acc[4][4][4];
#pragma unroll
    for (int a = 0; a < 4; a++)
#pragma unroll
        for (int b = 0; b < 4; b++)
#pragma unroll
            for (int c = 0; c < 4; c++) acc[a][b][c] = 0.f;

    // global load indices: 512 float4 per tile, 2 per thread
    const int r0 = (tid + 0) >> 2,   c0 = (tid + 0) & 3;
    const int r1 = (tid + 256) >> 2, c1 = (tid + 256) & 3;

    float4 a4[2], b4[2];
    a4[0] = *(const float4*)(A + (size_t)(bm + r0) * K + c0 * 4);
    a4[1] = *(const float4*)(A + (size_t)(bm + r1) * K + c1 * 4);
    b4[0] = *(const float4*)(B + (size_t)(bn + r0) * K + c0 * 4);
    b4[1] = *(const float4*)(B + (size_t)(bn + r1) * K + c1 * 4);

    const uint32_t ah_b = smaddr(Ah), al_b = smaddr(Al);
    const uint32_t bh_b = smaddr(Bh), bl_b = smaddr(Bl);

    const int nsteps = K >> 4;
    for (int kt = 0; kt < nsteps; kt++) {
        __syncthreads();
        {
            uint32_t h[2], l[2];
            split4(a4[0], h, l);
            *(uint2*)&Ah[r0 * GST + c0 * 4] = make_uint2(h[0], h[1]);
            *(uint2*)&Al[r0 * GST + c0 * 4] = make_uint2(l[0], l[1]);
            split4(a4[1], h, l);
            *(uint2*)&Ah[r1 * GST + c1 * 4] = make_uint2(h[0], h[1]);
            *(uint2*)&Al[r1 * GST + c1 * 4] = make_uint2(l[0], l[1]);
            split4(b4[0], h, l);
            *(uint2*)&Bh[r0 * GST + c0 * 4] = make_uint2(h[0], h[1]);
            *(uint2*)&Bl[r0 * GST + c0 * 4] = make_uint2(l[0], l[1]);
            split4(b4[1], h, l);
            *(uint2*)&Bh[r1 * GST + c1 * 4] = make_uint2(h[0], h[1]);
            *(uint2*)&Bl[r1 * GST + c1 * 4] = make_uint2(l[0], l[1]);
        }
        __syncthreads();

        if (kt + 1 < nsteps) {
            int ko = (kt + 1) * 16;
            a4[0] = *(const float4*)(A + (size_t)(bm + r0) * K + ko + c0 * 4);
            a4[1] = *(const float4*)(A + (size_t)(bm + r1) * K + ko + c1 * 4);
            b4[0] = *(const float4*)(B + (size_t)(bn + r0) * K + ko + c0 * 4);
            b4[1] = *(const float4*)(B + (size_t)(bn + r1) * K + ko + c1 * 4);
        }

        // A fragments: rows wr*64 + mt*16
        uint32_t fah[4][4], fal[4][4];
        {
            int row = wr * 64 + (lane & 15);
            int ko = (lane >> 4) * 8;
#pragma unroll
            for (int mt = 0; mt < 4; mt++) {
                uint32_t off = (uint32_t)(((row + mt * 16) * GST + ko) * 2);
                ldsm_x4(fah[mt], ah_b + off);
                ldsm_x4(fal[mt], al_b + off);
            }
        }
        // B fragments: ntile pairs p: n rows wc*32 + p*16
        uint32_t fbh[2][4], fbl[2][4];
        {
            int row = wc * 32 + (lane & 7) + ((lane >> 4) << 3);
            int ko = ((lane >> 3) & 1) * 8;
#pragma unroll
            for (int p = 0; p < 2; p++) {
                uint32_t off = (uint32_t)(((row + p * 16) * GST + ko) * 2);
                ldsm_x4(fbh[p], bh_b + off);
                ldsm_x4(fbl[p], bl_b + off);
            }
        }
#pragma unroll
        for (int mt = 0; mt < 4; mt++) {
#pragma unroll
            for (int p = 0; p < 2; p++) {
                mma_bf16(acc[mt][2 * p],     fah[mt], fbh[p][0], fbh[p][1]);
                mma_bf16(acc[mt][2 * p],     fah[mt], fbl[p][0], fbl[p][1]);
                mma_bf16(acc[mt][2 * p],     fal[mt], fbh[p][0], fbh[p][1]);
                mma_bf16(acc[mt][2 * p + 1], fah[mt], fbh[p][2], fbh[p][3]);
                mma_bf16(acc[mt][2 * p + 1], fah[mt], fbl[p][2], fbl[p][3]);
                mma_bf16(acc[mt][2 * p + 1], fal[mt], fbh[p][2], fbh[p][3]);
            }
        }
    }

    // epilogue + bias
#pragma unroll
    for (int mt = 0; mt < 4; mt++) {
        int row = bm + wr * 64 + mt * 16 + g;
#pragma unroll
        for (int nt = 0; nt < 4; nt++) {
            int col = bn + wc * 32 + nt * 8 + 2 * tg;
            float bx = bias[col], by = bias[col + 1];
            *(float2*)&C[(size_t)row * N + col] =
                make_float2(acc[mt][nt][0] + bx, acc[mt][nt][1] + by);
            *(float2*)&C[(size_t)(row + 8) * N + col] =
                make_float2(acc[mt][nt][2] + bx, acc[mt][nt][3] + by);
        }
    }
}

// ============================================================
// Flash attention, bf16-split tensor cores.
// CTA: 1 head x 128 q rows, 8 warps (16 q rows each), 64-key tiles.
// ============================================================
#define AST 72   // smem row stride (elems): 64 + 8 pad

// element offsets in dynamic smem (bf16 units)
#define OQH 0
#define OQL (128 * AST)
#define OKH (2 * 128 * AST)
#define OKL (OKH + 64 * AST)
#define OVH (OKL + 64 * AST)
#define OVL (OVH + 64 * AST)
#define ATT_SMEM_ELEMS (OVL + 64 * AST)

__global__ __launch_bounds__(256)
void flash_attn_bf16s(const float* __restrict__ qkv, float* __restrict__ ctx)
{
    extern __shared__ __nv_bfloat16 sm[];

    const int h = blockIdx.y;
    const int qb = blockIdx.x;
    const int tid = threadIdx.x;
    const int w = tid >> 5, lane = tid & 31;
    const int g = lane >> 2, tg = lane & 3;

    const float* qbase = qkv + (size_t)qb * 128 * QKVDIM + h * DH;
    const float* kbase = qkv + DMODEL + (size_t)h * DH;
    const float* vbase = qkv + 2 * DMODEL + (size_t)h * DH;

    const uint32_t smb = smaddr(sm);

    // ---- load Q (128x64), scale 1/8, split to smem ----
#pragma unroll
    for (int i = 0; i < 8; i++) {
        int fi = tid + i * 256;          // 2048 float4 total
        int row = fi >> 4, c4 = fi & 15;
        float4 v = *(const float4*)(qbase + (size_t)row * QKVDIM + c4 * 4);
        v.x *= 0.125f; v.y *= 0.125f; v.z *= 0.125f; v.w *= 0.125f;
        uint32_t hh[2], ll[2];
        split4(v, hh, ll);
        *(uint2*)&sm[OQH + row * AST + c4 * 4] = make_uint2(hh[0], hh[1]);
        *(uint2*)&sm[OQL + row * AST + c4 * 4] = make_uint2(ll[0], ll[1]);
    }
    __syncthreads();

    // ---- Q fragments in registers (per warp: 16 rows x 64 k) ----
    uint32_t qh[4][4], ql[4][4];
    {
        int row = w * 16 + (lane & 15);
#pragma unroll
        for (int kk = 0; kk < 4; kk++) {
            uint32_t off = (uint32_t)((row * AST + kk * 16 + (lane >> 4) * 8) * 2);
            ldsm_x4(qh[kk], smb + OQH * 2 + off);
            ldsm_x4(ql[kk], smb + OQL * 2 + off);
        }
    }

    float m0 = -1e30f, m1 = -1e30f, l0 = 0.f, l1 = 0.f;
    float o[8][4];
#pragma unroll
    for (int t = 0; t < 8; t++)
#pragma unroll
        for (int c = 0; c < 4; c++) o[t][c] = 0.f;

    // K/V prefetch regs: 4 float4 each
    const int kr = tid >> 2, kc = tid & 3;   // covers rows 0..63, 4 f4-cols... need 16 cols
    // 64 rows x 16 f4 = 1024 f4 / 256 thr = 4 per tensor
    float4 kv[8];
#pragma unroll
    for (int i = 0; i < 4; i++) {
        int fi = tid + i * 256;
        int row = fi >> 4, c4 = fi & 15;
        kv[i]     = *(const float4*)(kbase + (size_t)row * QKVDIM + c4 * 4);
        kv[4 + i] = *(const float4*)(vbase + (size_t)row * QKVDIM + c4 * 4);
    }

    for (int kt = 0; kt < SEQ / 64; kt++) {
        __syncthreads();
        // store K,V (split) to smem
#pragma unroll
        for (int i = 0; i < 4; i++) {
            int fi = tid + i * 256;
            int row = fi >> 4, c4 = fi & 15;
            uint32_t hh[2], ll[2];
            split4(kv[i], hh, ll);
            *(uint2*)&sm[OKH + row * AST + c4 * 4] = make_uint2(hh[0], hh[1]);
            *(uint2*)&sm[OKL + row * AST + c4 * 4] = make_uint2(ll[0], ll[1]);
            split4(kv[4 + i], hh, ll);
            *(uint2*)&sm[OVH + row * AST + c4 * 4] = make_uint2(hh[0], hh[1]);
            *(uint2*)&sm[OVL + row * AST + c4 * 4] = make_uint2(ll[0], ll[1]);
        }
        __syncthreads();

        // prefetch next K/V tile
        if (kt + 1 < SEQ / 64) {
            size_t rofs = (size_t)(kt + 1) * 64 * QKVDIM;
#pragma unroll
            for (int i = 0; i < 4; i++) {
                int fi = tid + i * 256;
                int row = fi >> 4, c4 = fi & 15;
                kv[i]     = *(const float4*)(kbase + rofs + (size_t)row * QKVDIM + c4 * 4);
                kv[4 + i] = *(const float4*)(vbase + rofs + (size_t)row * QKVDIM + c4 * 4);
            }
        }

        // ---- S = Q K^T : per warp 16x64, 8 ntiles ----
        float s[8][4];
#pragma unroll
        for (int t = 0; t < 8; t++)
#pragma unroll
            for (int c = 0; c < 4; c++) s[t][c] = 0.f;

#pragma unroll
        for (int kk = 0; kk < 4; kk++) {
            int nrow = (lane & 7) + ((lane >> 4) << 3);
            int ko = kk * 16 + ((lane >> 3) & 1) * 8;
            uint32_t kbh[4][4], kbl[4][4];
#pragma unroll
            for (int p = 0; p < 4; p++) {
                uint32_t off = (uint32_t)(((nrow + p * 16) * AST + ko) * 2);
                ldsm_x4(kbh[p], smb + OKH * 2 + off);
                ldsm_x4(kbl[p], smb + OKL * 2 + off);
            }
#pragma unroll
            for (int p = 0; p < 4; p++) {
                mma_bf16(s[2 * p],     qh[kk], kbh[p][0], kbh[p][1]);
                mma_bf16(s[2 * p],     qh[kk], kbl[p][0], kbl[p][1]);
                mma_bf16(s[2 * p],     ql[kk], kbh[p][0], kbh[p][1]);
                mma_bf16(s[2 * p + 1], qh[kk], kbh[p][2], kbh[p][3]);
                mma_bf16(s[2 * p + 1], qh[kk], kbl[p][2], kbl[p][3]);
                mma_bf16(s[2 * p + 1], ql[kk], kbh[p][2], kbh[p][3]);
            }
        }

        // ---- online softmax (rows: g and g+8; 4 lanes/row share cols) ----
        {
            float mx = s[0][0];
#pragma unroll
            for (int t = 0; t < 8; t++) { mx = fmaxf(mx, fmaxf(s[t][0], s[t][1])); }
            mx = fmaxf(mx, __shfl_xor_sync(0xffffffffu, mx, 1));
            mx = fmaxf(mx, __shfl_xor_sync(0xffffffffu, mx, 2));
            float mn = fmaxf(m0, mx);
            float corr = __expf(m0 - mn);
            float sum = 0.f;
#pragma unroll
            for (int t = 0; t < 8; t++) {
                s[t][0] = __expf(s[t][0] - mn);
                s[t][1] = __expf(s[t][1] - mn);
                sum += s[t][0] + s[t][1];
            }
            sum += __shfl_xor_sync(0xffffffffu, sum, 1);
            sum += __shfl_xor_sync(0xffffffffu, sum, 2);
            l0 = l0 * corr + sum; m0 = mn;
#pragma unroll
            for (int t = 0; t < 8; t++) { o[t][0] *= corr; o[t][1] *= corr; }
        }
        {
            float mx = s[0][2];
#pragma unroll
            for (int t = 0; t < 8; t++) { mx = fmaxf(mx, fmaxf(s[t][2], s[t][3])); }
            mx = fmaxf(mx, __shfl_xor_sync(0xffffffffu, mx, 1));
            mx = fmaxf(mx, __shfl_xor_sync(0xffffffffu, mx, 2));
            float mn = fmaxf(m1, mx);
            float corr = __expf(m1 - mn);
            float sum = 0.f;
#pragma unroll
            for (int t = 0; t < 8; t++) {
                s[t][2] = __expf(s[t][2] - mn);
                s[t][3] = __expf(s[t][3] - mn);
                sum += s[t][2] + s[t][3];
            }
            sum += __shfl_xor_sync(0xffffffffu, sum, 1);
            sum += __shfl_xor_sync(0xffffffffu, sum, 2);
            l1 = l1 * corr + sum; m1 = mn;
#pragma unroll
            for (int t = 0; t < 8; t++) { o[t][2] *= corr; o[t][3] *= corr; }
        }

        // ---- pack P fragments (S accum layout == A frag layout) ----
        uint32_t pah[4][4], pal[4][4];
#pragma unroll
        for (int t2 = 0; t2 < 4; t2++) {
            split2(s[2 * t2][0],     s[2 * t2][1],     pah[t2][0], pal[t2][0]);
            split2(s[2 * t2][2],     s[2 * t2][3],     pah[t2][1], pal[t2][1]);
            split2(s[2 * t2 + 1][0], s[2 * t2 + 1][1], pah[t2][2], pal[t2][2]);
            split2(s[2 * t2 + 1][2], s[2 * t2 + 1][3], pah[t2][3], pal[t2][3]);
        }

        // ---- O += P V : V fragments via ldmatrix.trans ----
#pragma unroll
        for (int kk2 = 0; kk2 < 4; kk2++) {
            int krow = kk2 * 16 + (lane & 15);
            int no = (lane >> 4) * 8;
            uint32_t vbh[4][4], vbl[4][4];
#pragma unroll
            for (int p = 0; p < 4; p++) {
                uint32_t off = (uint32_t)((krow * AST + p * 16 + no) * 2);
                ldsm_x4_t(vbh[p], smb + OVH * 2 + off);
                ldsm_x4_t(vbl[p], smb + OVL * 2 + off);
            }
#pragma unroll
            for (int p = 0; p < 4; p++) {
                mma_bf16(o[2 * p],     pah[kk2], vbh[p][0], vbh[p][1]);
                mma_bf16(o[2 * p],     pah[kk2], vbl[p][0], vbl[p][1]);
                mma_bf16(o[2 * p],     pal[kk2], vbh[p][0], vbh[p][1]);
                mma_bf16(o[2 * p + 1], pah[kk2], vbh[p][2], vbh[p][3]);
                mma_bf16(o[2 * p + 1], pah[kk2], vbl[p][2], vbl[p][3]);
                mma_bf16(o[2 * p + 1], pal[kk2], vbh[p][2], vbh[p][3]);
            }
        }
    }

    // ---- epilogue ----
    float inv0 = 1.0f / l0, inv1 = 1.0f / l1;
    int row0 = qb * 128 + w * 16 + g;
#pragma unroll
    for (int t = 0; t < 8; t++) {
        int d = h * DH + 8 * t + 2 * tg;
        *(float2*)&ctx[(size_t)row0 * DMODEL + d] =
            make_float2(o[t][0] * inv0, o[t][1] * inv0);
        *(float2*)&ctx[(size_t)(row0 + 8) * DMODEL + d] =
            make_float2(o[t][2] * inv1, o[t][3] * inv1);
    }
}

// ============================================================
extern "C" void kernel_launch(void* const* d_in, const int* in_sizes, int n_in,
                              void* d_out, int out_size)
{
    const float* x     = (const float*)d_in[0];
    const float* w_qkv = (const float*)d_in[1];
    const float* b_qkv = (const float*)d_in[2];
    const float* w_out = (const float*)d_in[3];
    const float* b_out = (const float*)d_in[4];
    float* out = (float*)d_out;

    float* qkv;  cudaGetSymbolAddress((void**)&qkv, g_qkv);
    float* ctx;  cudaGetSymbolAddress((void**)&ctx, g_ctx);

    // 1) QKV projection
    {
        dim3 grid(QKVDIM / 128, SEQ / 128);
        gemm_bf16s<<<grid, 256>>>(x, w_qkv, b_qkv, qkv, SEQ, QKVDIM, DMODEL);
    }
    // 2) flash attention
    {
        int smem = ATT_SMEM_ELEMS * 2;   // 73728 B
        cudaFuncSetAttribute(flash_attn_bf16s,
                             cudaFuncAttributeMaxDynamicSharedMemorySize, smem);
        dim3 grid(SEQ / 128, NHEADS);
        flash_attn_bf16s<<<grid, 256, smem>>>(qkv, ctx);
    }
    // 3) output projection
    {
        dim3 grid(DMODEL / 128, SEQ / 128);
        gemm_bf16s<<<grid, 256>>>(ctx, w_out, b_out, out, SEQ, DMODEL, DMODEL);
    }
}